// round 1
// baseline (speedup 1.0000x reference)
#include <cuda_runtime.h>
#include <cstdint>

#define E_DIM   512
#define W_DIM   16
#define FRAMES  16000
#define NBC     16              // 8 * 2 batch-channel rows
#define OUT_PER_BC 128008       // 8*(16000-1)+16
#define TPB     128
#define FPT     2               // frames per thread

__device__ __forceinline__ uint64_t fma2(uint64_t a, uint64_t b, uint64_t c) {
    uint64_t d;
    asm("fma.rn.f32x2 %0, %1, %2, %3;" : "=l"(d) : "l"(a), "l"(b), "l"(c));
    return d;
}
__device__ __forceinline__ uint64_t pack2(float lo, float hi) {
    uint64_t v;
    asm("mov.b64 %0, {%1, %2};" : "=l"(v) : "f"(lo), "f"(hi));
    return v;
}
__device__ __forceinline__ float redsum2(uint64_t v) {
    float lo, hi;
    asm("mov.b64 {%0, %1}, %2;" : "=f"(lo), "=f"(hi) : "l"(v));
    return lo + hi;
}

__global__ void zero_kernel(float4* __restrict__ out, int n4) {
    int i = blockIdx.x * blockDim.x + threadIdx.x;
    if (i < n4) out[i] = make_float4(0.f, 0.f, 0.f, 0.f);
}

__global__ __launch_bounds__(TPB)
void decoder_kernel(const float* __restrict__ mw,
                    const float* __restrict__ bw,
                    float* __restrict__ out)
{
    // sw[ep][w] = packed f32x2 ( bw[w][2ep], bw[w][2ep+1] )
    __shared__ uint64_t sw[E_DIM / 2][W_DIM];

    for (int i = threadIdx.x; i < (E_DIM / 2) * W_DIM; i += TPB) {
        int ep = i / W_DIM;
        int w  = i % W_DIM;
        sw[ep][w] = pack2(bw[w * E_DIM + 2 * ep], bw[w * E_DIM + 2 * ep + 1]);
    }
    __syncthreads();

    int g = blockIdx.x * TPB + threadIdx.x;
    const int tpbc = FRAMES / FPT;          // 8000 threads per (b,c)
    int bc = g / tpbc;
    int tf = g - bc * tpbc;
    long long k0 = (long long)tf * FPT;     // first frame owned by this thread

    const float4* base =
        (const float4*)(mw + ((long long)bc * FRAMES + k0) * E_DIM);

    uint64_t acc[FPT][W_DIM];
    #pragma unroll
    for (int f = 0; f < FPT; ++f)
        #pragma unroll
        for (int w = 0; w < W_DIM; ++w) acc[f][w] = 0ull;

    #pragma unroll 2
    for (int e4 = 0; e4 < E_DIM / 4; ++e4) {
        float4 xv[FPT];
        #pragma unroll
        for (int f = 0; f < FPT; ++f)
            xv[f] = __ldg(base + f * (E_DIM / 4) + e4);

        #pragma unroll
        for (int h = 0; h < 2; ++h) {       // ep = 2*e4 + h
            const int ep = 2 * e4 + h;
            uint64_t x2[FPT];
            #pragma unroll
            for (int f = 0; f < FPT; ++f) {
                float a = h ? xv[f].z : xv[f].x;
                float b = h ? xv[f].w : xv[f].y;
                x2[f] = pack2(a, b);
            }
            const ulonglong2* wp = (const ulonglong2*)&sw[ep][0];
            #pragma unroll
            for (int q = 0; q < 8; ++q) {   // 2 w's at a time via LDS.128
                ulonglong2 lw = wp[q];
                #pragma unroll
                for (int f = 0; f < FPT; ++f) {
                    acc[f][2 * q]     = fma2(x2[f], lw.x, acc[f][2 * q]);
                    acc[f][2 * q + 1] = fma2(x2[f], lw.y, acc[f][2 * q + 1]);
                }
            }
        }
    }

    // reduce e-even/e-odd halves
    float est[FPT][W_DIM];
    #pragma unroll
    for (int f = 0; f < FPT; ++f)
        #pragma unroll
        for (int w = 0; w < W_DIM; ++w)
            est[f][w] = redsum2(acc[f][w]);

    float* obase = out + (long long)bc * OUT_PER_BC;

    // interior subframe s = k0+1: both contributions local -> plain store
    #pragma unroll
    for (int j = 0; j < 8; ++j)
        obase[(k0 + 1) * 8 + j] = est[1][j] + est[0][8 + j];

    // boundary subframes s = k0 and s = k0+2: shared with neighbor threads
    #pragma unroll
    for (int j = 0; j < 8; ++j) {
        atomicAdd(&obase[k0 * 8 + j],       est[0][j]);
        atomicAdd(&obase[(k0 + 2) * 8 + j], est[1][8 + j]);
    }
}

extern "C" void kernel_launch(void* const* d_in, const int* in_sizes, int n_in,
                              void* d_out, int out_size) {
    const float* mw = (const float*)d_in[0];   // mixture_w [8,2,16000,512] f32
    const float* bw = (const float*)d_in[1];   // basis_weight [16,512] f32
    float* out = (float*)d_out;                // [8,2,128008] f32

    int n4 = out_size / 4;                     // 512032 float4's, exact
    zero_kernel<<<(n4 + 255) / 256, 256>>>((float4*)out, n4);

    int total_threads = NBC * (FRAMES / FPT);  // 128000
    decoder_kernel<<<total_threads / TPB, TPB>>>(mw, bw, out);
}

// round 3
// speedup vs baseline: 1.6994x; 1.6994x over previous
#include <cuda_runtime.h>
#include <cstdint>

#define E_DIM 512
#define W_DIM 16
#define FRAMES 16000
#define NBC 16
#define OUT_PER_BC 128008
#define GROUPS_PER_BC 1000
#define TOTAL_GROUPS 16000
#define G_PER_CTA 8
#define NCTA (TOTAL_GROUPS / G_PER_CTA)   // 2000
#define TPB 128

// Prepacked weight fragments, laid out [term][ws][lane] with term = ks*4+nh*2+b
__device__ uint32_t gBhi[4096];
__device__ uint32_t gBlo[4096];

__device__ __forceinline__ uint32_t bf16hi2(float x0, float x1) {
    uint32_t h;
    asm("cvt.rn.bf16x2.f32 %0, %1, %2;" : "=r"(h) : "f"(x1), "f"(x0));
    return h;  // low half = x0, high half = x1
}
__device__ __forceinline__ uint32_t bf16lo2(float x0, float x1, uint32_t h) {
    float h0 = __uint_as_float(h << 16);
    float h1 = __uint_as_float(h & 0xFFFF0000u);
    uint32_t l;
    asm("cvt.rn.bf16x2.f32 %0, %1, %2;" : "=r"(l) : "f"(x1 - h1), "f"(x0 - h0));
    return l;
}
__device__ __forceinline__ void hmma(float c[4],
                                     uint32_t a0, uint32_t a1, uint32_t a2, uint32_t a3,
                                     uint32_t b0, uint32_t b1) {
    asm volatile(
        "mma.sync.aligned.m16n8k16.row.col.f32.bf16.bf16.f32 "
        "{%0,%1,%2,%3}, {%4,%5,%6,%7}, {%8,%9}, {%0,%1,%2,%3};"
        : "+f"(c[0]), "+f"(c[1]), "+f"(c[2]), "+f"(c[3])
        : "r"(a0), "r"(a1), "r"(a2), "r"(a3), "r"(b0), "r"(b1));
}

__global__ void zero_kernel(float4* __restrict__ out, int n4) {
    int i = blockIdx.x * blockDim.x + threadIdx.x;
    if (i < n4) out[i] = make_float4(0.f, 0.f, 0.f, 0.f);
}

// Pack basis_weight [16,512] f32 into bf16 hi/lo mma B-fragments.
// Fragment element for (ws, lane, ks, nh, b): n = (lane>>2)+nh*8,
// k = ws*128 + ks*16 + (lane&3)*2 + b*8, pair (k, k+1) packed in one u32.
__global__ void pack_weights(const float* __restrict__ bw) {
    int idx = blockIdx.x * blockDim.x + threadIdx.x;
    if (idx >= 4096) return;
    int lane = idx & 31;
    int rest = idx >> 5;       // term*4 + ws
    int ws = rest & 3;
    int term = rest >> 2;      // ks*4 + nh*2 + b
    int b = term & 1;
    int nh = (term >> 1) & 1;
    int ks = term >> 2;
    int n = (lane >> 2) + nh * 8;
    int k = ws * 128 + ks * 16 + (lane & 3) * 2 + b * 8;
    float x0 = bw[n * E_DIM + k];
    float x1 = bw[n * E_DIM + k + 1];
    uint32_t hi = bf16hi2(x0, x1);
    gBhi[idx] = hi;
    gBlo[idx] = bf16lo2(x0, x1, hi);
}

__global__ __launch_bounds__(TPB, 4)
void decoder_hmma(const float* __restrict__ mw, float* __restrict__ out)
{
    __shared__ float part[4][16][16];   // per-warp K-slice partials
    __shared__ float est[16][16];

    const int tid = threadIdx.x;
    const int ws = tid >> 5;           // warp = K-slice 0..3
    const int lane = tid & 31;
    const int r = lane >> 2;           // fragment row group
    const int c0 = (lane & 3) * 2;     // fragment col pair base

    // ---- weight fragments: resident in registers for the whole CTA
    uint32_t bh[8][2][2], bl[8][2][2];
    #pragma unroll
    for (int ks = 0; ks < 8; ++ks)
        #pragma unroll
        for (int nh = 0; nh < 2; ++nh)
            #pragma unroll
            for (int b = 0; b < 2; ++b) {
                int term = ks * 4 + nh * 2 + b;
                bh[ks][nh][b] = gBhi[(term * 4 + ws) * 32 + lane];
                bl[ks][nh][b] = gBlo[(term * 4 + ws) * 32 + lane];
            }

    for (int g = 0; g < G_PER_CTA; ++g) {
        int group = blockIdx.x * G_PER_CTA + g;
        int bc = group / GROUPS_PER_BC;
        int gi = group - bc * GROUPS_PER_BC;
        long long f0 = (long long)gi * 16;

        const float* p0 = mw + ((long long)bc * FRAMES + f0 + r) * E_DIM + ws * 128 + c0;
        const float* p1 = p0 + 8 * E_DIM;

        float c[2][4] = {{0.f, 0.f, 0.f, 0.f}, {0.f, 0.f, 0.f, 0.f}};

        #pragma unroll
        for (int ks = 0; ks < 8; ++ks) {
            const float* q0 = p0 + ks * 16;
            const float* q1 = p1 + ks * 16;
            float2 x0 = *(const float2*)(q0);       // (r,    c0..c0+1)
            float2 x1 = *(const float2*)(q0 + 8);   // (r,    c0+8..9)
            float2 x2 = *(const float2*)(q1);       // (r+8,  c0..c0+1)
            float2 x3 = *(const float2*)(q1 + 8);   // (r+8,  c0+8..9)

            uint32_t ah0 = bf16hi2(x0.x, x0.y), al0 = bf16lo2(x0.x, x0.y, ah0);
            uint32_t ah1 = bf16hi2(x2.x, x2.y), al1 = bf16lo2(x2.x, x2.y, ah1);
            uint32_t ah2 = bf16hi2(x1.x, x1.y), al2 = bf16lo2(x1.x, x1.y, ah2);
            uint32_t ah3 = bf16hi2(x3.x, x3.y), al3 = bf16lo2(x3.x, x3.y, ah3);

            #pragma unroll
            for (int nh = 0; nh < 2; ++nh) {
                hmma(c[nh], ah0, ah1, ah2, ah3, bh[ks][nh][0], bh[ks][nh][1]);
                hmma(c[nh], ah0, ah1, ah2, ah3, bl[ks][nh][0], bl[ks][nh][1]);
                hmma(c[nh], al0, al1, al2, al3, bh[ks][nh][0], bh[ks][nh][1]);
            }
        }

        // ---- cross-warp K reduction via SMEM
        #pragma unroll
        for (int nh = 0; nh < 2; ++nh) {
            *(float2*)&part[ws][r][c0 + nh * 8]     = make_float2(c[nh][0], c[nh][1]);
            *(float2*)&part[ws][r + 8][c0 + nh * 8] = make_float2(c[nh][2], c[nh][3]);
        }
        __syncthreads();

        #pragma unroll
        for (int h = 0; h < 2; ++h) {
            int e = tid + h * 128;
            int rr = e >> 4, cc = e & 15;
            est[rr][cc] = part[0][rr][cc] + part[1][rr][cc]
                        + part[2][rr][cc] + part[3][rr][cc];
        }
        __syncthreads();

        // ---- overlap-add (frame_length 16, step 8)
        float* ob = out + (long long)bc * OUT_PER_BC + f0 * 8;
        if (tid < 120) {
            int k = tid >> 3, j = tid & 7;
            ob[(k + 1) * 8 + j] = est[k][8 + j] + est[k + 1][j];
        }
        if (tid < 8)
            atomicAdd(ob + tid, est[0][tid]);
        else if (tid < 16)
            atomicAdd(ob + 128 + (tid - 8), est[15][8 + (tid - 8)]);
        __syncthreads();
    }
}

extern "C" void kernel_launch(void* const* d_in, const int* in_sizes, int n_in,
                              void* d_out, int out_size) {
    const float* mw = (const float*)d_in[0];   // [8,2,16000,512] f32
    const float* bw = (const float*)d_in[1];   // [16,512] f32
    float* out = (float*)d_out;                // [8,2,128008] f32

    int n4 = out_size / 4;
    zero_kernel<<<(n4 + 255) / 256, 256>>>((float4*)out, n4);
    pack_weights<<<32, 128>>>(bw);
    decoder_hmma<<<NCTA, TPB>>>(mw, out);
}

// round 4
// speedup vs baseline: 1.8950x; 1.1151x over previous
#include <cuda_runtime.h>
#include <cstdint>

#define E_DIM 512
#define W_DIM 16
#define FRAMES 16000
#define NBC 16
#define OUT_PER_BC 128008
#define GROUPS_PER_BC 1000
#define TOTAL_GROUPS 16000
#define G_PER_CTA 8
#define NCTA (TOTAL_GROUPS / G_PER_CTA)   // 2000
#define TPB 128

// Prepacked weight fragments, [term][ws][lane], term = ks*4 + nh*2 + b
__device__ uint32_t gBhi[4096];
__device__ uint32_t gBlo[4096];

__device__ __forceinline__ uint32_t bf16hi2(float x0, float x1) {
    uint32_t h;
    asm("cvt.rn.bf16x2.f32 %0, %1, %2;" : "=r"(h) : "f"(x1), "f"(x0));
    return h;
}
__device__ __forceinline__ uint32_t bf16lo2(float x0, float x1, uint32_t h) {
    float h0 = __uint_as_float(h << 16);
    float h1 = __uint_as_float(h & 0xFFFF0000u);
    uint32_t l;
    asm("cvt.rn.bf16x2.f32 %0, %1, %2;" : "=r"(l) : "f"(x1 - h1), "f"(x0 - h0));
    return l;
}
__device__ __forceinline__ void hmma(float c[4],
                                     uint32_t a0, uint32_t a1, uint32_t a2, uint32_t a3,
                                     uint32_t b0, uint32_t b1) {
    asm volatile(
        "mma.sync.aligned.m16n8k16.row.col.f32.bf16.bf16.f32 "
        "{%0,%1,%2,%3}, {%4,%5,%6,%7}, {%8,%9}, {%0,%1,%2,%3};"
        : "+f"(c[0]), "+f"(c[1]), "+f"(c[2]), "+f"(c[3])
        : "r"(a0), "r"(a1), "r"(a2), "r"(a3), "r"(b0), "r"(b1));
}
__device__ __forceinline__ void ldsm4(uint32_t a[4], uint32_t addr) {
    asm volatile("ldmatrix.sync.aligned.m8n8.x4.shared.b16 {%0,%1,%2,%3}, [%4];"
                 : "=r"(a[0]), "=r"(a[1]), "=r"(a[2]), "=r"(a[3]) : "r"(addr));
}
__device__ __forceinline__ void sts64(uint32_t addr, uint32_t a, uint32_t b) {
    asm volatile("st.shared.v2.b32 [%0], {%1, %2};" :: "r"(addr), "r"(a), "r"(b) : "memory");
}
__device__ __forceinline__ uint32_t smem_u32(const void* p) {
    uint32_t a;
    asm("{ .reg .u64 t; cvta.to.shared.u64 t, %1; cvt.u32.u64 %0, t; }" : "=r"(a) : "l"(p));
    return a;
}

// zero only CTA-boundary subframes: per bc, offsets c*1024 + j (c=0..125, j<8)
__global__ void zero_boundaries(float* __restrict__ out) {
    int i = blockIdx.x * blockDim.x + threadIdx.x;   // 16*126*8 = 16128
    if (i >= NBC * 126 * 8) return;
    int j = i & 7;
    int c = (i >> 3) % 126;
    int bc = i / (126 * 8);
    out[(long long)bc * OUT_PER_BC + c * 1024 + j] = 0.f;
}

__global__ void pack_weights(const float* __restrict__ bw) {
    int idx = blockIdx.x * blockDim.x + threadIdx.x;
    if (idx >= 4096) return;
    int lane = idx & 31;
    int rest = idx >> 5;
    int ws = rest & 3;
    int term = rest >> 2;
    int b = term & 1;
    int nh = (term >> 1) & 1;
    int ks = term >> 2;
    int n = (lane >> 2) + nh * 8;
    int k = ws * 128 + ks * 16 + (lane & 3) * 2 + b * 8;
    float x0 = bw[n * E_DIM + k];
    float x1 = bw[n * E_DIM + k + 1];
    uint32_t hi = bf16hi2(x0, x1);
    gBhi[idx] = hi;
    gBlo[idx] = bf16lo2(x0, x1, hi);
}

__global__ __launch_bounds__(TPB, 3)
void decoder_hmma(const float* __restrict__ mw, float* __restrict__ out)
{
    // per-warp A tiles: 16 rows x 128 bf16 (256 B/row), hi then lo, 8 KB/warp
    __shared__ __align__(16) char sA[4 * 8192];
    __shared__ float part[4][16][16];
    __shared__ float est[16][16];
    __shared__ float carry[8];

    const int tid = threadIdx.x;
    const int ws = tid >> 5;
    const int lane = tid & 31;
    const int r = lane >> 2;
    const int c0 = (lane & 3) * 2;

    const uint32_t hiB = smem_u32(sA) + ws * 8192;
    const uint32_t loB = hiB + 4096;

    // weight fragments resident in registers
    uint32_t bh[8][2][2], bl[8][2][2];
    #pragma unroll
    for (int ks = 0; ks < 8; ++ks)
        #pragma unroll
        for (int nh = 0; nh < 2; ++nh)
            #pragma unroll
            for (int b = 0; b < 2; ++b) {
                int term = ks * 4 + nh * 2 + b;
                bh[ks][nh][b] = gBhi[(term * 4 + ws) * 32 + lane];
                bl[ks][nh][b] = gBlo[(term * 4 + ws) * 32 + lane];
            }

    const int bc = (blockIdx.x * G_PER_CTA) / GROUPS_PER_BC;
    const int gi0 = (blockIdx.x * G_PER_CTA) - bc * GROUPS_PER_BC;
    float* const obc = out + (long long)bc * OUT_PER_BC;

    // precomputed swizzled STS offset within a row (lane-dependent)
    // and ldmatrix lane address row/chunksel
    const int lrow = lane & 15;
    const int lcs = (lane >> 4) & 1;

    for (int g = 0; g < G_PER_CTA; ++g) {
        const long long f0 = (long long)(gi0 + g) * 16;
        const float* gsrc = mw + ((long long)bc * FRAMES + f0) * E_DIM + ws * 128;

        // ---- stage A: coalesced LDG.128, cvt, swizzled STS (2 batches of 8 rows)
        #pragma unroll
        for (int batch = 0; batch < 2; ++batch) {
            float4 v[8];
            #pragma unroll
            for (int i = 0; i < 8; ++i)
                v[i] = *(const float4*)(gsrc + (long long)(batch * 8 + i) * E_DIM + lane * 4);
            #pragma unroll
            for (int i = 0; i < 8; ++i) {
                int row = batch * 8 + i;
                uint32_t h0 = bf16hi2(v[i].x, v[i].y), h1 = bf16hi2(v[i].z, v[i].w);
                uint32_t l0 = bf16lo2(v[i].x, v[i].y, h0), l1 = bf16lo2(v[i].z, v[i].w, h1);
                uint32_t byte = (uint32_t)row * 256
                              + (uint32_t)(((lane >> 1) ^ (row & 7)) * 16)
                              + (uint32_t)((lane & 1) * 8);
                sts64(hiB + byte, h0, h1);
                sts64(loB + byte, l0, l1);
            }
        }
        __syncwarp();

        // ---- compute: ldmatrix fragments + 3-pass split-precision HMMA
        float c[2][4] = {{0.f, 0.f, 0.f, 0.f}, {0.f, 0.f, 0.f, 0.f}};
        #pragma unroll
        for (int ks = 0; ks < 8; ++ks) {
            int chunk = 2 * ks + lcs;
            uint32_t byte = (uint32_t)lrow * 256 + (uint32_t)((chunk ^ (lrow & 7)) * 16);
            uint32_t ah[4], al[4];
            ldsm4(ah, hiB + byte);
            ldsm4(al, loB + byte);
            #pragma unroll
            for (int nh = 0; nh < 2; ++nh) {
                hmma(c[nh], ah[0], ah[1], ah[2], ah[3], bh[ks][nh][0], bh[ks][nh][1]);
                hmma(c[nh], ah[0], ah[1], ah[2], ah[3], bl[ks][nh][0], bl[ks][nh][1]);
                hmma(c[nh], al[0], al[1], al[2], al[3], bh[ks][nh][0], bh[ks][nh][1]);
            }
        }

        // ---- cross-warp K reduction
        #pragma unroll
        for (int nh = 0; nh < 2; ++nh) {
            *(float2*)&part[ws][r][c0 + nh * 8]     = make_float2(c[nh][0], c[nh][1]);
            *(float2*)&part[ws][r + 8][c0 + nh * 8] = make_float2(c[nh][2], c[nh][3]);
        }
        __syncthreads();

        #pragma unroll
        for (int h = 0; h < 2; ++h) {
            int e = tid + h * 128;
            int rr = e >> 4, cc = e & 15;
            est[rr][cc] = part[0][rr][cc] + part[1][rr][cc]
                        + part[2][rr][cc] + part[3][rr][cc];
        }
        __syncthreads();

        // ---- overlap-add with carry across sequential groups
        float* ob = obc + f0 * 8;
        if (tid < 120) {
            int k = tid >> 3, j = tid & 7;
            ob[(k + 1) * 8 + j] = est[k][8 + j] + est[k + 1][j];
        }
        if (tid < 8) {
            if (g == 0) atomicAdd(ob + tid, est[0][tid]);
            else        ob[tid] = carry[tid] + est[0][tid];
            carry[tid] = est[15][8 + tid];
        }
        __syncthreads();
    }

    // final CTA-edge boundary
    if (tid < 8) {
        float* obl = obc + (long long)(gi0 + G_PER_CTA - 1) * 128;
        atomicAdd(obl + 128 + tid, carry[tid]);
    }
}

extern "C" void kernel_launch(void* const* d_in, const int* in_sizes, int n_in,
                              void* d_out, int out_size) {
    const float* mw = (const float*)d_in[0];   // [8,2,16000,512] f32
    const float* bw = (const float*)d_in[1];   // [16,512] f32
    float* out = (float*)d_out;                // [8,2,128008] f32

    zero_boundaries<<<(NBC * 126 * 8 + 127) / 128, 128>>>(out);
    pack_weights<<<32, 128>>>(bw);
    decoder_hmma<<<NCTA, TPB>>>(mw, out);
}